// round 11
// baseline (speedup 1.0000x reference)
#include <cuda_runtime.h>
#include <cuda_bf16.h>
#include <cstdint>

// Problem constants
#define MODEL_DIM 1024
#define NHEAD     16
#define HDIM      64
#define BATCH     2
#define SEQ       2048
#define MROWS     (BATCH * SEQ)   // 4096

// ===========================================================================
// Scratch (device globals — allocation-free per harness rules)
// ===========================================================================
__device__ float g_O[MROWS * MODEL_DIM];
__device__ __nv_bfloat16 g_Ahi[MROWS * MODEL_DIM];
__device__ __nv_bfloat16 g_Alo[MROWS * MODEL_DIM];
__device__ __nv_bfloat16 g_Bhi[MODEL_DIM * MODEL_DIM];   // W^T hi  [n][k]
__device__ __nv_bfloat16 g_Blo[MODEL_DIM * MODEL_DIM];   // W^T lo  [n][k]
__device__ __nv_bfloat16 g_Qhi[MROWS * MODEL_DIM];
__device__ __nv_bfloat16 g_Qlo[MROWS * MODEL_DIM];
__device__ __nv_bfloat16 g_Khi[MROWS * MODEL_DIM];
__device__ __nv_bfloat16 g_Klo[MROWS * MODEL_DIM];
__device__ __nv_bfloat16 g_Vhi[MROWS * MODEL_DIM];
__device__ __nv_bfloat16 g_Vlo[MROWS * MODEL_DIM];
__device__ __nv_bfloat16 g_mb[SEQ * SEQ];

// ===========================================================================
// Helpers (base sm_103 ISA: ldmatrix + mma.sync + cp.async)
// ===========================================================================
__device__ __forceinline__ uint32_t smem_u32(const void* p) {
    uint32_t a;
    asm("{ .reg .u64 t; cvta.to.shared.u64 t, %1; cvt.u32.u64 %0, t; }"
        : "=r"(a) : "l"(p));
    return a;
}

#define SMEM_SWIZZLE_128B(o) ((o) ^ (((o) >> 3) & 0x70))

__device__ __forceinline__ void cp_async16(uint32_t dst, const void* src) {
    asm volatile("cp.async.cg.shared.global [%0], [%1], 16;"
                 :: "r"(dst), "l"(src) : "memory");
}
#define CP_COMMIT() asm volatile("cp.async.commit_group;" ::: "memory")
#define CP_WAIT(n)  asm volatile("cp.async.wait_group %0;" :: "n"(n) : "memory")

__device__ __forceinline__ void ldsm_x4(uint32_t* r, uint32_t addr) {
    asm volatile("ldmatrix.sync.aligned.m8n8.x4.shared.b16 {%0,%1,%2,%3}, [%4];"
                 : "=r"(r[0]), "=r"(r[1]), "=r"(r[2]), "=r"(r[3]) : "r"(addr));
}
__device__ __forceinline__ void ldsm_x4_t(uint32_t* r, uint32_t addr) {
    asm volatile("ldmatrix.sync.aligned.m8n8.x4.trans.shared.b16 {%0,%1,%2,%3}, [%4];"
                 : "=r"(r[0]), "=r"(r[1]), "=r"(r[2]), "=r"(r[3]) : "r"(addr));
}
__device__ __forceinline__ void ldsm_x2(uint32_t* r, uint32_t addr) {
    asm volatile("ldmatrix.sync.aligned.m8n8.x2.shared.b16 {%0,%1}, [%2];"
                 : "=r"(r[0]), "=r"(r[1]) : "r"(addr));
}
__device__ __forceinline__ void mma16816(float* c, const uint32_t* a,
                                         const uint32_t* b) {
    asm volatile(
        "mma.sync.aligned.m16n8k16.row.col.f32.bf16.bf16.f32 "
        "{%0,%1,%2,%3}, {%4,%5,%6,%7}, {%8,%9}, {%0,%1,%2,%3};"
        : "+f"(c[0]), "+f"(c[1]), "+f"(c[2]), "+f"(c[3])
        : "r"(a[0]), "r"(a[1]), "r"(a[2]), "r"(a[3]), "r"(b[0]), "r"(b[1]));
}

__device__ __forceinline__ void split_pack(uint32_t& h, uint32_t& l,
                                           float x, float y) {
    __nv_bfloat162 h2 = __floats2bfloat162_rn(x, y);
    float lx = x - __bfloat162float(h2.x);
    float ly = y - __bfloat162float(h2.y);
    __nv_bfloat162 l2 = __floats2bfloat162_rn(lx, ly);
    h = *reinterpret_cast<uint32_t*>(&h2);
    l = *reinterpret_cast<uint32_t*>(&l2);
}

// ===========================================================================
// Conversion kernels
// ===========================================================================
__global__ __launch_bounds__(256) void conv_act(
    const float4* __restrict__ X,
    __nv_bfloat162* __restrict__ hi2, __nv_bfloat162* __restrict__ lo2) {
    int i = blockIdx.x * 256 + threadIdx.x;
    float4 x = X[i];
    __nv_bfloat16 h0 = __float2bfloat16_rn(x.x);
    __nv_bfloat16 h1 = __float2bfloat16_rn(x.y);
    __nv_bfloat16 h2 = __float2bfloat16_rn(x.z);
    __nv_bfloat16 h3 = __float2bfloat16_rn(x.w);
    __nv_bfloat16 l0 = __float2bfloat16_rn(x.x - __bfloat162float(h0));
    __nv_bfloat16 l1 = __float2bfloat16_rn(x.y - __bfloat162float(h1));
    __nv_bfloat16 l2 = __float2bfloat16_rn(x.z - __bfloat162float(h2));
    __nv_bfloat16 l3 = __float2bfloat16_rn(x.w - __bfloat162float(h3));
    hi2[2 * i + 0] = __nv_bfloat162(h0, h1);
    hi2[2 * i + 1] = __nv_bfloat162(h2, h3);
    lo2[2 * i + 0] = __nv_bfloat162(l0, l1);
    lo2[2 * i + 1] = __nv_bfloat162(l2, l3);
}

__global__ __launch_bounds__(256) void conv_wt(
    const float* __restrict__ W,
    __nv_bfloat16* __restrict__ Thi, __nv_bfloat16* __restrict__ Tlo) {
    __shared__ float t[32][33];
    int n0 = blockIdx.x * 32, k0 = blockIdx.y * 32;
    int tx = threadIdx.x, ty = threadIdx.y;   // block (32, 8)
#pragma unroll
    for (int i = 0; i < 4; i++)
        t[ty + 8 * i][tx] = W[(size_t)(k0 + ty + 8 * i) * MODEL_DIM + n0 + tx];
    __syncthreads();
#pragma unroll
    for (int i = 0; i < 4; i++) {
        float x = t[tx][ty + 8 * i];
        __nv_bfloat16 h = __float2bfloat16_rn(x);
        __nv_bfloat16 l = __float2bfloat16_rn(x - __bfloat162float(h));
        size_t off = (size_t)(n0 + ty + 8 * i) * MODEL_DIM + k0 + tx;
        Thi[off] = h;
        Tlo[off] = l;
    }
}

__global__ __launch_bounds__(256) void conv_mask(
    const int4* __restrict__ m, __nv_bfloat162* __restrict__ out2) {
    int i = blockIdx.x * 256 + threadIdx.x;
    int4 v = m[i];
    const float NEG = -1e4f;
    out2[2 * i + 0] = __floats2bfloat162_rn(v.x ? 0.f : NEG, v.y ? 0.f : NEG);
    out2[2 * i + 1] = __floats2bfloat162_rn(v.z ? 0.f : NEG, v.w ? 0.f : NEG);
}

// ===========================================================================
// HMMA GEMM, cp.async double-buffered.
// CTA tile 64(M) x 128(N), BK=64, 256 threads (8 warps, warp tile 32x32).
// Stage = AH(8K) AL(8K) BH(16K) BL(16K) = 48KB; x2 stages = 96KB smem.
// ===========================================================================
#define GS_AH 0
#define GS_AL 8192
#define GS_BH 16384
#define GS_BL 32768
#define G_STAGE 49152
#define G_SMEM_TOTAL (2 * G_STAGE)

__device__ __forceinline__ void gemm_load_chunk(
    uint32_t sb, int stage,
    const __nv_bfloat16* __restrict__ Ahi, const __nv_bfloat16* __restrict__ Alo,
    const __nv_bfloat16* __restrict__ Bhi, const __nv_bfloat16* __restrict__ Blo,
    int m0, int n0, int k0, int tid) {
    uint32_t base = sb + stage * G_STAGE;
    // A tiles: 64 rows x 128B
#pragma unroll
    for (int it = 0; it < 2; it++) {
        int t = tid + it * 256;               // 0..511
        int row = t >> 3, seg = t & 7;
        uint32_t off = SMEM_SWIZZLE_128B(row * 128 + seg * 16);
        size_t src = (size_t)(m0 + row) * MODEL_DIM + k0 + seg * 8;
        cp_async16(base + GS_AH + off, Ahi + src);
        cp_async16(base + GS_AL + off, Alo + src);
    }
    // B tiles: 128 rows x 128B
#pragma unroll
    for (int it = 0; it < 4; it++) {
        int t = tid + it * 256;               // 0..1023
        int row = t >> 3, seg = t & 7;
        uint32_t off = SMEM_SWIZZLE_128B(row * 128 + seg * 16);
        size_t src = (size_t)(n0 + row) * MODEL_DIM + k0 + seg * 8;
        cp_async16(base + GS_BH + off, Bhi + src);
        cp_async16(base + GS_BL + off, Blo + src);
    }
}

template <bool SPLIT_OUT>
__global__ __launch_bounds__(256) void gemm_tc(
    const __nv_bfloat16* __restrict__ Ahi, const __nv_bfloat16* __restrict__ Alo,
    const __nv_bfloat16* __restrict__ Bhi, const __nv_bfloat16* __restrict__ Blo,
    const float* __restrict__ bias, float* __restrict__ C,
    __nv_bfloat16* __restrict__ Chi, __nv_bfloat16* __restrict__ Clo) {
    extern __shared__ char smem[];
    uint32_t sb = smem_u32(smem);
    const int tid = threadIdx.x;
    const int wid = tid >> 5;
    const int lane = tid & 31;
    const int warp_m = wid >> 2;              // 0..1 -> 32-row slab
    const int warp_n = wid & 3;               // 0..3 -> 32-col slab
    const int m0 = blockIdx.y * 64;
    const int n0 = blockIdx.x * 128;

    float acc[2][4][4];
#pragma unroll
    for (int i = 0; i < 2; i++)
#pragma unroll
        for (int j = 0; j < 4; j++)
#pragma unroll
            for (int f = 0; f < 4; f++) acc[i][j][f] = 0.f;

    const int a_row = lane & 15;
    const int a_kb = (lane >> 4) << 4;
    const int b_row = lane & 7;
    const int b_kb = ((lane >> 3) & 1) << 4;

    gemm_load_chunk(sb, 0, Ahi, Alo, Bhi, Blo, m0, n0, 0, tid);
    CP_COMMIT();

#pragma unroll 1
    for (int ck = 0; ck < MODEL_DIM / 64; ck++) {
        const int cur = ck & 1;
        if (ck < MODEL_DIM / 64 - 1) {
            gemm_load_chunk(sb, 1 - cur, Ahi, Alo, Bhi, Blo,
                            m0, n0, (ck + 1) * 64, tid);
            CP_COMMIT();
            CP_WAIT(1);
        } else {
            CP_WAIT(0);
        }
        __syncthreads();

        uint32_t base = sb + cur * G_STAGE;
#pragma unroll
        for (int ks = 0; ks < 4; ks++) {
            uint32_t ah[2][4], al[2][4], bh[4][2], bl[4][2];
#pragma unroll
            for (int mt = 0; mt < 2; mt++) {
                int row = warp_m * 32 + mt * 16 + a_row;
                uint32_t sw = SMEM_SWIZZLE_128B(row * 128 + ks * 32 + a_kb);
                ldsm_x4(ah[mt], base + GS_AH + sw);
                ldsm_x4(al[mt], base + GS_AL + sw);
            }
#pragma unroll
            for (int nt = 0; nt < 4; nt++) {
                int row = warp_n * 32 + nt * 8 + b_row;
                uint32_t sw = SMEM_SWIZZLE_128B(row * 128 + ks * 32 + b_kb);
                ldsm_x2(bh[nt], base + GS_BH + sw);
                ldsm_x2(bl[nt], base + GS_BL + sw);
            }
#pragma unroll
            for (int mt = 0; mt < 2; mt++)
#pragma unroll
                for (int nt = 0; nt < 4; nt++) {
                    mma16816(acc[mt][nt], ah[mt], bh[nt]);
                    mma16816(acc[mt][nt], ah[mt], bl[nt]);
                    mma16816(acc[mt][nt], al[mt], bh[nt]);
                }
        }
        __syncthreads();
    }

    const int g = lane >> 2;
    const int tq = (lane & 3) * 2;
#pragma unroll
    for (int mt = 0; mt < 2; mt++)
#pragma unroll
        for (int nt = 0; nt < 4; nt++) {
            int m = m0 + warp_m * 32 + mt * 16 + g;
            int n = n0 + warp_n * 32 + nt * 8 + tq;
            float2 bb = *(const float2*)(bias + n);
            float v00 = acc[mt][nt][0] + bb.x, v01 = acc[mt][nt][1] + bb.y;
            float v10 = acc[mt][nt][2] + bb.x, v11 = acc[mt][nt][3] + bb.y;
            if (SPLIT_OUT) {
                uint32_t h0, l0v, h1, l1v;
                split_pack(h0, l0v, v00, v01);
                split_pack(h1, l1v, v10, v11);
                *(uint32_t*)(Chi + (size_t)m * MODEL_DIM + n) = h0;
                *(uint32_t*)(Clo + (size_t)m * MODEL_DIM + n) = l0v;
                *(uint32_t*)(Chi + (size_t)(m + 8) * MODEL_DIM + n) = h1;
                *(uint32_t*)(Clo + (size_t)(m + 8) * MODEL_DIM + n) = l1v;
            } else {
                *(float2*)(C + (size_t)m * MODEL_DIM + n) = make_float2(v00, v01);
                *(float2*)(C + (size_t)(m + 8) * MODEL_DIM + n) = make_float2(v10, v11);
            }
        }
}

// ===========================================================================
// Tensor-core flash attention (HMMA, bf16x3) — unchanged from R9.
// ===========================================================================
#define AT_OFF_KH 0
#define AT_OFF_KL 8192
#define AT_OFF_VH 16384
#define AT_OFF_VL 24576
#define AT_SMEM   32768

__global__ __launch_bounds__(128) void attn_tc() {
    extern __shared__ char smc[];
    uint32_t sb = smem_u32(smc);
    const int tid = threadIdx.x;
    const int lane = tid & 31;
    const int w = tid >> 5;
    const int qt = blockIdx.x;
    const int bh = blockIdx.y;
    const int b = bh >> 4, h = bh & 15;
    const size_t qtok = (size_t)(b * SEQ + qt * 64);
    const size_t ktok = (size_t)(b * SEQ);

    {
        const __nv_bfloat16* Qh = g_Qhi + qtok * MODEL_DIM + h * HDIM;
        const __nv_bfloat16* Ql = g_Qlo + qtok * MODEL_DIM + h * HDIM;
#pragma unroll
        for (int i = 0; i < 4; i++) {
            int t = tid + i * 128;
            int r = t >> 3, s8 = t & 7;
            uint32_t dst = SMEM_SWIZZLE_128B(r * 128 + s8 * 16);
            *(uint4*)(smc + AT_OFF_KH + dst) =
                *(const uint4*)(Qh + (size_t)r * MODEL_DIM + s8 * 8);
            *(uint4*)(smc + AT_OFF_KL + dst) =
                *(const uint4*)(Ql + (size_t)r * MODEL_DIM + s8 * 8);
        }
    }
    __syncthreads();
    uint32_t qh[4][4], ql[4][4];
    {
        int ar = lane & 15, akb = (lane >> 4) << 4;
#pragma unroll
        for (int ks = 0; ks < 4; ks++) {
            uint32_t off = SMEM_SWIZZLE_128B((w * 16 + ar) * 128 + ks * 32 + akb);
            ldsm_x4(qh[ks], sb + AT_OFF_KH + off);
            ldsm_x4(ql[ks], sb + AT_OFF_KL + off);
        }
    }
    __syncthreads();

    float m0 = -1e30f, m1 = -1e30f, l0 = 0.f, l1 = 0.f;
    float o[8][4];
#pragma unroll
    for (int i = 0; i < 8; i++)
#pragma unroll
        for (int j = 0; j < 4; j++) o[i][j] = 0.f;

    const __nv_bfloat16* Kh = g_Khi + ktok * MODEL_DIM + h * HDIM;
    const __nv_bfloat16* Kl = g_Klo + ktok * MODEL_DIM + h * HDIM;
    const __nv_bfloat16* Vh = g_Vhi + ktok * MODEL_DIM + h * HDIM;
    const __nv_bfloat16* Vl = g_Vlo + ktok * MODEL_DIM + h * HDIM;

    const int g = lane >> 2;
    const int tq2 = (lane & 3) * 2;
    const int krow_in = ((lane >> 4) << 3) + (lane & 7);
    const int kkb = ((lane >> 3) & 1) << 4;
    const int vk_in = (((lane >> 3) & 1) << 3) + (lane & 7);
    const int vd_in = (lane >> 4) << 3;

    const __nv_bfloat16* mbrow = g_mb + (size_t)(qt * 64 + w * 16 + g) * SEQ + tq2;

    for (int kt = 0; kt < SEQ / 64; kt++) {
        {
            const size_t toff = (size_t)(kt * 64);
#pragma unroll
            for (int i = 0; i < 4; i++) {
                int t = tid + i * 128;
                int r = t >> 3, s8 = t & 7;
                uint32_t dst = SMEM_SWIZZLE_128B(r * 128 + s8 * 16);
                size_t src = (toff + r) * MODEL_DIM + s8 * 8;
                *(uint4*)(smc + AT_OFF_KH + dst) = *(const uint4*)(Kh + src);
                *(uint4*)(smc + AT_OFF_KL + dst) = *(const uint4*)(Kl + src);
                *(uint4*)(smc + AT_OFF_VH + dst) = *(const uint4*)(Vh + src);
                *(uint4*)(smc + AT_OFF_VL + dst) = *(const uint4*)(Vl + src);
            }
        }
        __syncthreads();

        float s[8][4];
#pragma unroll
        for (int i = 0; i < 8; i++)
#pragma unroll
            for (int j = 0; j < 4; j++) s[i][j] = 0.f;

#pragma unroll
        for (int ks = 0; ks < 4; ks++) {
#pragma unroll
            for (int ntp = 0; ntp < 4; ntp++) {
                uint32_t off = SMEM_SWIZZLE_128B((ntp * 16 + krow_in) * 128 +
                                                 ks * 32 + kkb);
                uint32_t bhf[4], blf[4];
                ldsm_x4(bhf, sb + AT_OFF_KH + off);
                ldsm_x4(blf, sb + AT_OFF_KL + off);
                mma16816(s[2 * ntp], qh[ks], bhf + 0);
                mma16816(s[2 * ntp], qh[ks], blf + 0);
                mma16816(s[2 * ntp], ql[ks], bhf + 0);
                mma16816(s[2 * ntp + 1], qh[ks], bhf + 2);
                mma16816(s[2 * ntp + 1], qh[ks], blf + 2);
                mma16816(s[2 * ntp + 1], ql[ks], bhf + 2);
            }
        }

        const float scale = 0.125f;
        const __nv_bfloat16* mb = mbrow + kt * 64;
#pragma unroll
        for (int nt = 0; nt < 8; nt++) {
            uint32_t u0 = *(const uint32_t*)(mb + nt * 8);
            uint32_t u1 = *(const uint32_t*)(mb + 8 * SEQ + nt * 8);
            float2 f0 = __bfloat1622float2(*reinterpret_cast<__nv_bfloat162*>(&u0));
            float2 f1 = __bfloat1622float2(*reinterpret_cast<__nv_bfloat162*>(&u1));
            s[nt][0] = s[nt][0] * scale + f0.x;
            s[nt][1] = s[nt][1] * scale + f0.y;
            s[nt][2] = s[nt][2] * scale + f1.x;
            s[nt][3] = s[nt][3] * scale + f1.y;
        }

        float rm0 = -1e30f, rm1 = -1e30f;
#pragma unroll
        for (int nt = 0; nt < 8; nt++) {
            rm0 = fmaxf(rm0, fmaxf(s[nt][0], s[nt][1]));
            rm1 = fmaxf(rm1, fmaxf(s[nt][2], s[nt][3]));
        }
        rm0 = fmaxf(rm0, __shfl_xor_sync(0xffffffffu, rm0, 1));
        rm0 = fmaxf(rm0, __shfl_xor_sync(0xffffffffu, rm0, 2));
        rm1 = fmaxf(rm1, __shfl_xor_sync(0xffffffffu, rm1, 1));
        rm1 = fmaxf(rm1, __shfl_xor_sync(0xffffffffu, rm1, 2));
        float mn0 = fmaxf(m0, rm0), mn1 = fmaxf(m1, rm1);
        float a0 = __expf(m0 - mn0), a1 = __expf(m1 - mn1);
        float rs0 = 0.f, rs1 = 0.f;
#pragma unroll
        for (int nt = 0; nt < 8; nt++) {
            s[nt][0] = __expf(s[nt][0] - mn0);
            s[nt][1] = __expf(s[nt][1] - mn0);
            s[nt][2] = __expf(s[nt][2] - mn1);
            s[nt][3] = __expf(s[nt][3] - mn1);
            rs0 += s[nt][0] + s[nt][1];
            rs1 += s[nt][2] + s[nt][3];
        }
        rs0 += __shfl_xor_sync(0xffffffffu, rs0, 1);
        rs0 += __shfl_xor_sync(0xffffffffu, rs0, 2);
        rs1 += __shfl_xor_sync(0xffffffffu, rs1, 1);
        rs1 += __shfl_xor_sync(0xffffffffu, rs1, 2);
        l0 = l0 * a0 + rs0; m0 = mn0;
        l1 = l1 * a1 + rs1; m1 = mn1;
#pragma unroll
        for (int nd = 0; nd < 8; nd++) {
            o[nd][0] *= a0; o[nd][1] *= a0;
            o[nd][2] *= a1; o[nd][3] *= a1;
        }

        uint32_t ph[4][4], pl[4][4];
#pragma unroll
        for (int j = 0; j < 4; j++) {
            split_pack(ph[j][0], pl[j][0], s[2 * j][0], s[2 * j][1]);
            split_pack(ph[j][1], pl[j][1], s[2 * j][2], s[2 * j][3]);
            split_pack(ph[j][2], pl[j][2], s[2 * j + 1][0], s[2 * j + 1][1]);
            split_pack(ph[j][3], pl[j][3], s[2 * j + 1][2], s[2 * j + 1][3]);
        }

#pragma unroll
        for (int j = 0; j < 4; j++) {
#pragma unroll
            for (int ndp = 0; ndp < 4; ndp++) {
                uint32_t off = SMEM_SWIZZLE_128B((j * 16 + vk_in) * 128 +
                                                 (ndp * 16 + vd_in) * 2);
                uint32_t vh4[4], vl4[4];
                ldsm_x4_t(vh4, sb + AT_OFF_VH + off);
                ldsm_x4_t(vl4, sb + AT_OFF_VL + off);
                mma16816(o[2 * ndp], ph[j], vh4 + 0);
                mma16816(o[2 * ndp], ph[j], vl4 + 0);
                mma16816(o[2 * ndp], pl[j], vh4 + 0);
                mma16816(o[2 * ndp + 1], ph[j], vh4 + 2);
                mma16816(o[2 * ndp + 1], ph[j], vl4 + 2);
                mma16816(o[2 * ndp + 1], pl[j], vh4 + 2);
            }
        }
        __syncthreads();
    }

    float i0 = 1.f / l0, i1 = 1.f / l1;
    float* Og = g_O + (qtok + w * 16 + g) * MODEL_DIM + h * HDIM + tq2;
#pragma unroll
    for (int nd = 0; nd < 8; nd++) {
        *(float2*)(Og + nd * 8) = make_float2(o[nd][0] * i0, o[nd][1] * i0);
        *(float2*)(Og + 8 * MODEL_DIM + nd * 8) =
            make_float2(o[nd][2] * i1, o[nd][3] * i1);
    }
}

// ===========================================================================
// Launch
// ===========================================================================
extern "C" void kernel_launch(void* const* d_in, const int* in_sizes, int n_in,
                              void* d_out, int out_size) {
    const float* q   = (const float*)d_in[0];
    const float* k   = (const float*)d_in[1];
    const float* v   = (const float*)d_in[2];
    const int*   msk = (const int*)  d_in[3];
    const float* w_q = (const float*)d_in[4];
    const float* b_q = (const float*)d_in[5];
    const float* w_k = (const float*)d_in[6];
    const float* b_k = (const float*)d_in[7];
    const float* w_v = (const float*)d_in[8];
    const float* b_v = (const float*)d_in[9];
    const float* w_o = (const float*)d_in[10];
    const float* b_o = (const float*)d_in[11];
    float* out = (float*)d_out;

    float* pO;
    __nv_bfloat16 *pAhi, *pAlo, *pBhi, *pBlo;
    __nv_bfloat16 *pQh, *pQl, *pKh, *pKl, *pVh, *pVl, *pMB;
    cudaGetSymbolAddress((void**)&pO, g_O);
    cudaGetSymbolAddress((void**)&pAhi, g_Ahi);
    cudaGetSymbolAddress((void**)&pAlo, g_Alo);
    cudaGetSymbolAddress((void**)&pBhi, g_Bhi);
    cudaGetSymbolAddress((void**)&pBlo, g_Blo);
    cudaGetSymbolAddress((void**)&pQh, g_Qhi);
    cudaGetSymbolAddress((void**)&pQl, g_Qlo);
    cudaGetSymbolAddress((void**)&pKh, g_Khi);
    cudaGetSymbolAddress((void**)&pKl, g_Klo);
    cudaGetSymbolAddress((void**)&pVh, g_Vhi);
    cudaGetSymbolAddress((void**)&pVl, g_Vlo);
    cudaGetSymbolAddress((void**)&pMB, g_mb);

    cudaFuncSetAttribute(gemm_tc<true>,
                         cudaFuncAttributeMaxDynamicSharedMemorySize, G_SMEM_TOTAL);
    cudaFuncSetAttribute(gemm_tc<false>,
                         cudaFuncAttributeMaxDynamicSharedMemorySize, G_SMEM_TOTAL);

    const int act_blocks = (MROWS * MODEL_DIM / 4) / 256;   // 4096
    dim3 wt_grid(MODEL_DIM / 32, MODEL_DIM / 32);
    dim3 wt_block(32, 8);
    dim3 g_grid(MODEL_DIM / 128, MROWS / 64);               // (8, 64)

    conv_mask<<<(SEQ * SEQ / 4) / 256, 256>>>((const int4*)msk,
                                              (__nv_bfloat162*)pMB);

    // Q projection -> bf16 hi/lo
    conv_act<<<act_blocks, 256>>>((const float4*)q,
                                  (__nv_bfloat162*)pAhi, (__nv_bfloat162*)pAlo);
    conv_wt<<<wt_grid, wt_block>>>(w_q, pBhi, pBlo);
    gemm_tc<true><<<g_grid, 256, G_SMEM_TOTAL>>>(pAhi, pAlo, pBhi, pBlo, b_q,
                                                 nullptr, pQh, pQl);
    // K projection -> bf16 hi/lo
    conv_act<<<act_blocks, 256>>>((const float4*)k,
                                  (__nv_bfloat162*)pAhi, (__nv_bfloat162*)pAlo);
    conv_wt<<<wt_grid, wt_block>>>(w_k, pBhi, pBlo);
    gemm_tc<true><<<g_grid, 256, G_SMEM_TOTAL>>>(pAhi, pAlo, pBhi, pBlo, b_k,
                                                 nullptr, pKh, pKl);
    // V projection -> bf16 hi/lo
    conv_act<<<act_blocks, 256>>>((const float4*)v,
                                  (__nv_bfloat162*)pAhi, (__nv_bfloat162*)pAlo);
    conv_wt<<<wt_grid, wt_block>>>(w_v, pBhi, pBlo);
    gemm_tc<true><<<g_grid, 256, G_SMEM_TOTAL>>>(pAhi, pAlo, pBhi, pBlo, b_v,
                                                 nullptr, pVh, pVl);

    // Tensor-core flash attention
    dim3 agrid(SEQ / 64, BATCH * NHEAD);                    // (32, 32)
    attn_tc<<<agrid, 128, AT_SMEM>>>();

    // Output projection (fp32 out)
    conv_act<<<act_blocks, 256>>>((const float4*)pO,
                                  (__nv_bfloat162*)pAhi, (__nv_bfloat162*)pAlo);
    conv_wt<<<wt_grid, wt_block>>>(w_o, pBhi, pBlo);
    gemm_tc<false><<<g_grid, 256, G_SMEM_TOTAL>>>(pAhi, pAlo, pBhi, pBlo, b_o,
                                                  out, nullptr, nullptr);
}

// round 13
// speedup vs baseline: 1.8135x; 1.8135x over previous
#include <cuda_runtime.h>
#include <cuda_bf16.h>
#include <cstdint>

// Problem constants
#define MODEL_DIM 1024
#define NHEAD     16
#define HDIM      64
#define BATCH     2
#define SEQ       2048
#define MROWS     (BATCH * SEQ)   // 4096

// ===========================================================================
// Scratch (device globals — allocation-free per harness rules)
// ===========================================================================
__device__ float g_O[MROWS * MODEL_DIM];
__device__ __nv_bfloat16 g_Ahi[MROWS * MODEL_DIM];
__device__ __nv_bfloat16 g_Alo[MROWS * MODEL_DIM];
__device__ __nv_bfloat16 g_Bhi[MODEL_DIM * MODEL_DIM];   // W^T hi  [n][k]
__device__ __nv_bfloat16 g_Blo[MODEL_DIM * MODEL_DIM];   // W^T lo  [n][k]
__device__ __nv_bfloat16 g_Qhi[MROWS * MODEL_DIM];
__device__ __nv_bfloat16 g_Qlo[MROWS * MODEL_DIM];
__device__ __nv_bfloat16 g_Khi[MROWS * MODEL_DIM];
__device__ __nv_bfloat16 g_Klo[MROWS * MODEL_DIM];
__device__ __nv_bfloat16 g_Vhi[MROWS * MODEL_DIM];
__device__ __nv_bfloat16 g_Vlo[MROWS * MODEL_DIM];
__device__ __nv_bfloat16 g_mb[SEQ * SEQ];

// ===========================================================================
// Helpers
// ===========================================================================
__device__ __forceinline__ uint32_t smem_u32(const void* p) {
    uint32_t a;
    asm("{ .reg .u64 t; cvta.to.shared.u64 t, %1; cvt.u32.u64 %0, t; }"
        : "=r"(a) : "l"(p));
    return a;
}

#define SMEM_SWIZZLE_128B(o) ((o) ^ (((o) >> 3) & 0x70))

__device__ __forceinline__ void cp_async16(uint32_t dst, const void* src) {
    asm volatile("cp.async.cg.shared.global [%0], [%1], 16;"
                 :: "r"(dst), "l"(src) : "memory");
}
#define CP_COMMIT() asm volatile("cp.async.commit_group;" ::: "memory")
#define CP_WAIT(n)  asm volatile("cp.async.wait_group %0;" :: "n"(n) : "memory")

__device__ __forceinline__ void ldsm_x4(uint32_t* r, uint32_t addr) {
    asm volatile("ldmatrix.sync.aligned.m8n8.x4.shared.b16 {%0,%1,%2,%3}, [%4];"
                 : "=r"(r[0]), "=r"(r[1]), "=r"(r[2]), "=r"(r[3]) : "r"(addr));
}
__device__ __forceinline__ void ldsm_x4_t(uint32_t* r, uint32_t addr) {
    asm volatile("ldmatrix.sync.aligned.m8n8.x4.trans.shared.b16 {%0,%1,%2,%3}, [%4];"
                 : "=r"(r[0]), "=r"(r[1]), "=r"(r[2]), "=r"(r[3]) : "r"(addr));
}
__device__ __forceinline__ void ldsm_x2(uint32_t* r, uint32_t addr) {
    asm volatile("ldmatrix.sync.aligned.m8n8.x2.shared.b16 {%0,%1}, [%2];"
                 : "=r"(r[0]), "=r"(r[1]) : "r"(addr));
}
__device__ __forceinline__ void mma16816(float* c, const uint32_t* a,
                                         const uint32_t* b) {
    asm volatile(
        "mma.sync.aligned.m16n8k16.row.col.f32.bf16.bf16.f32 "
        "{%0,%1,%2,%3}, {%4,%5,%6,%7}, {%8,%9}, {%0,%1,%2,%3};"
        : "+f"(c[0]), "+f"(c[1]), "+f"(c[2]), "+f"(c[3])
        : "r"(a[0]), "r"(a[1]), "r"(a[2]), "r"(a[3]), "r"(b[0]), "r"(b[1]));
}

__device__ __forceinline__ void split_pack(uint32_t& h, uint32_t& l,
                                           float x, float y) {
    __nv_bfloat162 h2 = __floats2bfloat162_rn(x, y);
    float lx = x - __bfloat162float(h2.x);
    float ly = y - __bfloat162float(h2.y);
    __nv_bfloat162 l2 = __floats2bfloat162_rn(lx, ly);
    h = *reinterpret_cast<uint32_t*>(&h2);
    l = *reinterpret_cast<uint32_t*>(&l2);
}

// ===========================================================================
// Conversion kernels
// ===========================================================================
__global__ __launch_bounds__(256) void conv_act(
    const float4* __restrict__ X,
    __nv_bfloat162* __restrict__ hi2, __nv_bfloat162* __restrict__ lo2) {
    int i = blockIdx.x * 256 + threadIdx.x;
    float4 x = X[i];
    __nv_bfloat16 h0 = __float2bfloat16_rn(x.x);
    __nv_bfloat16 h1 = __float2bfloat16_rn(x.y);
    __nv_bfloat16 h2 = __float2bfloat16_rn(x.z);
    __nv_bfloat16 h3 = __float2bfloat16_rn(x.w);
    __nv_bfloat16 l0 = __float2bfloat16_rn(x.x - __bfloat162float(h0));
    __nv_bfloat16 l1 = __float2bfloat16_rn(x.y - __bfloat162float(h1));
    __nv_bfloat16 l2 = __float2bfloat16_rn(x.z - __bfloat162float(h2));
    __nv_bfloat16 l3 = __float2bfloat16_rn(x.w - __bfloat162float(h3));
    hi2[2 * i + 0] = __nv_bfloat162(h0, h1);
    hi2[2 * i + 1] = __nv_bfloat162(h2, h3);
    lo2[2 * i + 0] = __nv_bfloat162(l0, l1);
    lo2[2 * i + 1] = __nv_bfloat162(l2, l3);
}

__global__ __launch_bounds__(256) void conv_wt(
    const float* __restrict__ W,
    __nv_bfloat16* __restrict__ Thi, __nv_bfloat16* __restrict__ Tlo) {
    __shared__ float t[32][33];
    int n0 = blockIdx.x * 32, k0 = blockIdx.y * 32;
    int tx = threadIdx.x, ty = threadIdx.y;   // block (32, 8)
#pragma unroll
    for (int i = 0; i < 4; i++)
        t[ty + 8 * i][tx] = W[(size_t)(k0 + ty + 8 * i) * MODEL_DIM + n0 + tx];
    __syncthreads();
#pragma unroll
    for (int i = 0; i < 4; i++) {
        float x = t[tx][ty + 8 * i];
        __nv_bfloat16 h = __float2bfloat16_rn(x);
        __nv_bfloat16 l = __float2bfloat16_rn(x - __bfloat162float(h));
        size_t off = (size_t)(n0 + ty + 8 * i) * MODEL_DIM + k0 + tx;
        Thi[off] = h;
        Tlo[off] = l;
    }
}

__global__ __launch_bounds__(256) void conv_mask(
    const int4* __restrict__ m, __nv_bfloat162* __restrict__ out2) {
    int i = blockIdx.x * 256 + threadIdx.x;
    int4 v = m[i];
    const float NEG = -1e4f;
    out2[2 * i + 0] = __floats2bfloat162_rn(v.x ? 0.f : NEG, v.y ? 0.f : NEG);
    out2[2 * i + 1] = __floats2bfloat162_rn(v.z ? 0.f : NEG, v.w ? 0.f : NEG);
}

// ===========================================================================
// HMMA GEMM, 2-stage cp.async pipeline, ONE __syncthreads per K-chunk.
// CTA 128x128, BK=64, 256 threads (8 warps, warp tile 64x32).
// Stage = AH/AL/BH/BL x 16KB = 64KB; x2 stages = 128KB smem.
// ===========================================================================
#define GS_AH 0
#define GS_AL 16384
#define GS_BH 32768
#define GS_BL 49152
#define G_STAGE 65536
#define G_SMEM_TOTAL (2 * G_STAGE)

__device__ __forceinline__ void gemm_load_chunk(
    uint32_t sb, int stage,
    const __nv_bfloat16* __restrict__ Ahi, const __nv_bfloat16* __restrict__ Alo,
    const __nv_bfloat16* __restrict__ Bhi, const __nv_bfloat16* __restrict__ Blo,
    int m0, int n0, int k0, int tid) {
    uint32_t base = sb + stage * G_STAGE;
#pragma unroll
    for (int it = 0; it < 4; it++) {
        int t = tid + it * 256;               // 0..1023
        int row = t >> 3, seg = t & 7;
        uint32_t off = SMEM_SWIZZLE_128B(row * 128 + seg * 16);
        size_t srcA = (size_t)(m0 + row) * MODEL_DIM + k0 + seg * 8;
        size_t srcB = (size_t)(n0 + row) * MODEL_DIM + k0 + seg * 8;
        cp_async16(base + GS_AH + off, Ahi + srcA);
        cp_async16(base + GS_AL + off, Alo + srcA);
        cp_async16(base + GS_BH + off, Bhi + srcB);
        cp_async16(base + GS_BL + off, Blo + srcB);
    }
}

template <bool SPLIT_OUT>
__global__ __launch_bounds__(256) void gemm_tc(
    const __nv_bfloat16* __restrict__ Ahi, const __nv_bfloat16* __restrict__ Alo,
    const __nv_bfloat16* __restrict__ Bhi, const __nv_bfloat16* __restrict__ Blo,
    const float* __restrict__ bias, float* __restrict__ C,
    __nv_bfloat16* __restrict__ Chi, __nv_bfloat16* __restrict__ Clo) {
    extern __shared__ char smem[];
    uint32_t sb = smem_u32(smem);
    const int tid = threadIdx.x;
    const int wid = tid >> 5;
    const int lane = tid & 31;
    const int warp_m = wid >> 2;              // 0..1 -> 64-row slab
    const int warp_n = wid & 3;               // 0..3 -> 32-col slab
    const int m0 = blockIdx.y * 128;
    const int n0 = blockIdx.x * 128;

    float acc[4][4][4];
#pragma unroll
    for (int i = 0; i < 4; i++)
#pragma unroll
        for (int j = 0; j < 4; j++)
#pragma unroll
            for (int f = 0; f < 4; f++) acc[i][j][f] = 0.f;

    const int a_row = lane & 15;
    const int a_kb = (lane >> 4) << 4;
    const int b_row = lane & 7;
    const int b_kb = ((lane >> 3) & 1) << 4;

    gemm_load_chunk(sb, 0, Ahi, Alo, Bhi, Blo, m0, n0, 0, tid);
    CP_COMMIT();

#pragma unroll 1
    for (int ck = 0; ck < MODEL_DIM / 64; ck++) {
        const int cur = ck & 1;
        CP_WAIT(0);
        __syncthreads();
        // Prefetch next chunk into the other stage. After the barrier, all
        // threads have finished computing chunk ck-1 (which used that stage),
        // so overwriting it is race-free.  One barrier per chunk total.
        if (ck < MODEL_DIM / 64 - 1) {
            gemm_load_chunk(sb, 1 - cur, Ahi, Alo, Bhi, Blo,
                            m0, n0, (ck + 1) * 64, tid);
            CP_COMMIT();
        }

        uint32_t base = sb + cur * G_STAGE;
#pragma unroll
        for (int ks = 0; ks < 4; ks++) {
            uint32_t ah[4][4], al[4][4], bh[4][2], bl[4][2];
#pragma unroll
            for (int mt = 0; mt < 4; mt++) {
                int row = warp_m * 64 + mt * 16 + a_row;
                uint32_t sw = SMEM_SWIZZLE_128B(row * 128 + ks * 32 + a_kb);
                ldsm_x4(ah[mt], base + GS_AH + sw);
                ldsm_x4(al[mt], base + GS_AL + sw);
            }
#pragma unroll
            for (int nt = 0; nt < 4; nt++) {
                int row = warp_n * 32 + nt * 8 + b_row;
                uint32_t sw = SMEM_SWIZZLE_128B(row * 128 + ks * 32 + b_kb);
                ldsm_x2(bh[nt], base + GS_BH + sw);
                ldsm_x2(bl[nt], base + GS_BL + sw);
            }
#pragma unroll
            for (int mt = 0; mt < 4; mt++)
#pragma unroll
                for (int nt = 0; nt < 4; nt++) {
                    mma16816(acc[mt][nt], ah[mt], bh[nt]);
                    mma16816(acc[mt][nt], ah[mt], bl[nt]);
                    mma16816(acc[mt][nt], al[mt], bh[nt]);
                }
        }
    }

    const int g = lane >> 2;
    const int tq = (lane & 3) * 2;
#pragma unroll
    for (int mt = 0; mt < 4; mt++)
#pragma unroll
        for (int nt = 0; nt < 4; nt++) {
            int m = m0 + warp_m * 64 + mt * 16 + g;
            int n = n0 + warp_n * 32 + nt * 8 + tq;
            float2 bb = *(const float2*)(bias + n);
            float v00 = acc[mt][nt][0] + bb.x, v01 = acc[mt][nt][1] + bb.y;
            float v10 = acc[mt][nt][2] + bb.x, v11 = acc[mt][nt][3] + bb.y;
            if (SPLIT_OUT) {
                uint32_t h0, l0v, h1, l1v;
                split_pack(h0, l0v, v00, v01);
                split_pack(h1, l1v, v10, v11);
                *(uint32_t*)(Chi + (size_t)m * MODEL_DIM + n) = h0;
                *(uint32_t*)(Clo + (size_t)m * MODEL_DIM + n) = l0v;
                *(uint32_t*)(Chi + (size_t)(m + 8) * MODEL_DIM + n) = h1;
                *(uint32_t*)(Clo + (size_t)(m + 8) * MODEL_DIM + n) = l1v;
            } else {
                *(float2*)(C + (size_t)m * MODEL_DIM + n) = make_float2(v00, v01);
                *(float2*)(C + (size_t)(m + 8) * MODEL_DIM + n) = make_float2(v10, v11);
            }
        }
}

// ===========================================================================
// Tensor-core flash attention (HMMA, bf16x3), 2-stage cp.async K/V pipeline.
// Block = 128 threads (4 warps) = 64 query rows for one (b,h).
// Stage = KH/KL/VH/VL x 8KB = 32KB; x2 = 64KB smem.
// ===========================================================================
#define AT_KH 0
#define AT_KL 8192
#define AT_VH 16384
#define AT_VL 24576
#define AT_STAGE 32768
#define AT_SMEM  (2 * AT_STAGE)

__device__ __forceinline__ void attn_load_chunk(
    uint32_t sb, int stage,
    const __nv_bfloat16* __restrict__ Kh, const __nv_bfloat16* __restrict__ Kl,
    const __nv_bfloat16* __restrict__ Vh, const __nv_bfloat16* __restrict__ Vl,
    int kt, int tid) {
    uint32_t base = sb + stage * AT_STAGE;
#pragma unroll
    for (int i = 0; i < 4; i++) {
        int t = tid + i * 128;
        int r = t >> 3, s8 = t & 7;
        uint32_t off = SMEM_SWIZZLE_128B(r * 128 + s8 * 16);
        size_t src = (size_t)(kt * 64 + r) * MODEL_DIM + s8 * 8;
        cp_async16(base + AT_KH + off, Kh + src);
        cp_async16(base + AT_KL + off, Kl + src);
        cp_async16(base + AT_VH + off, Vh + src);
        cp_async16(base + AT_VL + off, Vl + src);
    }
}

__global__ __launch_bounds__(128) void attn_tc() {
    extern __shared__ char smc[];
    uint32_t sb = smem_u32(smc);
    const int tid = threadIdx.x;
    const int lane = tid & 31;
    const int w = tid >> 5;
    const int qt = blockIdx.x;
    const int bh = blockIdx.y;
    const int b = bh >> 4, h = bh & 15;
    const size_t qtok = (size_t)(b * SEQ + qt * 64);
    const size_t ktok = (size_t)(b * SEQ);

    const __nv_bfloat16* Kh = g_Khi + ktok * MODEL_DIM + h * HDIM;
    const __nv_bfloat16* Kl = g_Klo + ktok * MODEL_DIM + h * HDIM;
    const __nv_bfloat16* Vh = g_Vhi + ktok * MODEL_DIM + h * HDIM;
    const __nv_bfloat16* Vl = g_Vlo + ktok * MODEL_DIM + h * HDIM;

    // ---- stage Q through stage-0 K region, extract fragments ----
    {
        const __nv_bfloat16* Qh = g_Qhi + qtok * MODEL_DIM + h * HDIM;
        const __nv_bfloat16* Ql = g_Qlo + qtok * MODEL_DIM + h * HDIM;
#pragma unroll
        for (int i = 0; i < 4; i++) {
            int t = tid + i * 128;
            int r = t >> 3, s8 = t & 7;
            uint32_t dst = SMEM_SWIZZLE_128B(r * 128 + s8 * 16);
            *(uint4*)(smc + AT_KH + dst) =
                *(const uint4*)(Qh + (size_t)r * MODEL_DIM + s8 * 8);
            *(uint4*)(smc + AT_KL + dst) =
                *(const uint4*)(Ql + (size_t)r * MODEL_DIM + s8 * 8);
        }
    }
    __syncthreads();
    uint32_t qh[4][4], ql[4][4];
    {
        int ar = lane & 15, akb = (lane >> 4) << 4;
#pragma unroll
        for (int ks = 0; ks < 4; ks++) {
            uint32_t off = SMEM_SWIZZLE_128B((w * 16 + ar) * 128 + ks * 32 + akb);
            ldsm_x4(qh[ks], sb + AT_KH + off);
            ldsm_x4(ql[ks], sb + AT_KL + off);
        }
    }
    __syncthreads();

    // prefetch kt=0 into stage 0 (Q already consumed into registers)
    attn_load_chunk(sb, 0, Kh, Kl, Vh, Vl, 0, tid);
    CP_COMMIT();

    float m0 = -1e30f, m1 = -1e30f, l0 = 0.f, l1 = 0.f;
    float o[8][4];
#pragma unroll
    for (int i = 0; i < 8; i++)
#pragma unroll
        for (int j = 0; j < 4; j++) o[i][j] = 0.f;

    const int g = lane >> 2;
    const int tq2 = (lane & 3) * 2;
    const int krow_in = ((lane >> 4) << 3) + (lane & 7);
    const int kkb = ((lane >> 3) & 1) << 4;
    const int vk_in = (((lane >> 3) & 1) << 3) + (lane & 7);
    const int vd_in = (lane >> 4) << 3;

    const __nv_bfloat16* mbrow = g_mb + (size_t)(qt * 64 + w * 16 + g) * SEQ + tq2;

#pragma unroll 1
    for (int kt = 0; kt < SEQ / 64; kt++) {
        const int cur = kt & 1;
        CP_WAIT(0);
        __syncthreads();
        if (kt < SEQ / 64 - 1) {
            attn_load_chunk(sb, 1 - cur, Kh, Kl, Vh, Vl, kt + 1, tid);
            CP_COMMIT();
        }
        uint32_t base = sb + cur * AT_STAGE;

        // ---- S = Q K^T (bf16x3) ----
        float s[8][4];
#pragma unroll
        for (int i = 0; i < 8; i++)
#pragma unroll
            for (int j = 0; j < 4; j++) s[i][j] = 0.f;

#pragma unroll
        for (int ks = 0; ks < 4; ks++) {
#pragma unroll
            for (int ntp = 0; ntp < 4; ntp++) {
                uint32_t off = SMEM_SWIZZLE_128B((ntp * 16 + krow_in) * 128 +
                                                 ks * 32 + kkb);
                uint32_t bhf[4], blf[4];
                ldsm_x4(bhf, base + AT_KH + off);
                ldsm_x4(blf, base + AT_KL + off);
                mma16816(s[2 * ntp], qh[ks], bhf + 0);
                mma16816(s[2 * ntp], qh[ks], blf + 0);
                mma16816(s[2 * ntp], ql[ks], bhf + 0);
                mma16816(s[2 * ntp + 1], qh[ks], bhf + 2);
                mma16816(s[2 * ntp + 1], qh[ks], blf + 2);
                mma16816(s[2 * ntp + 1], ql[ks], bhf + 2);
            }
        }

        // ---- scale + additive mask bias ----
        const float scale = 0.125f;
        const __nv_bfloat16* mb = mbrow + kt * 64;
#pragma unroll
        for (int nt = 0; nt < 8; nt++) {
            uint32_t u0 = *(const uint32_t*)(mb + nt * 8);
            uint32_t u1 = *(const uint32_t*)(mb + 8 * SEQ + nt * 8);
            float2 f0 = __bfloat1622float2(*reinterpret_cast<__nv_bfloat162*>(&u0));
            float2 f1 = __bfloat1622float2(*reinterpret_cast<__nv_bfloat162*>(&u1));
            s[nt][0] = s[nt][0] * scale + f0.x;
            s[nt][1] = s[nt][1] * scale + f0.y;
            s[nt][2] = s[nt][2] * scale + f1.x;
            s[nt][3] = s[nt][3] * scale + f1.y;
        }

        // ---- online softmax ----
        float rm0 = -1e30f, rm1 = -1e30f;
#pragma unroll
        for (int nt = 0; nt < 8; nt++) {
            rm0 = fmaxf(rm0, fmaxf(s[nt][0], s[nt][1]));
            rm1 = fmaxf(rm1, fmaxf(s[nt][2], s[nt][3]));
        }
        rm0 = fmaxf(rm0, __shfl_xor_sync(0xffffffffu, rm0, 1));
        rm0 = fmaxf(rm0, __shfl_xor_sync(0xffffffffu, rm0, 2));
        rm1 = fmaxf(rm1, __shfl_xor_sync(0xffffffffu, rm1, 1));
        rm1 = fmaxf(rm1, __shfl_xor_sync(0xffffffffu, rm1, 2));
        float mn0 = fmaxf(m0, rm0), mn1 = fmaxf(m1, rm1);
        float a0 = __expf(m0 - mn0), a1 = __expf(m1 - mn1);
        float rs0 = 0.f, rs1 = 0.f;
#pragma unroll
        for (int nt = 0; nt < 8; nt++) {
            s[nt][0] = __expf(s[nt][0] - mn0);
            s[nt][1] = __expf(s[nt][1] - mn0);
            s[nt][2] = __expf(s[nt][2] - mn1);
            s[nt][3] = __expf(s[nt][3] - mn1);
            rs0 += s[nt][0] + s[nt][1];
            rs1 += s[nt][2] + s[nt][3];
        }
        rs0 += __shfl_xor_sync(0xffffffffu, rs0, 1);
        rs0 += __shfl_xor_sync(0xffffffffu, rs0, 2);
        rs1 += __shfl_xor_sync(0xffffffffu, rs1, 1);
        rs1 += __shfl_xor_sync(0xffffffffu, rs1, 2);
        l0 = l0 * a0 + rs0; m0 = mn0;
        l1 = l1 * a1 + rs1; m1 = mn1;
#pragma unroll
        for (int nd = 0; nd < 8; nd++) {
            o[nd][0] *= a0; o[nd][1] *= a0;
            o[nd][2] *= a1; o[nd][3] *= a1;
        }

        // ---- pack P -> A fragments ----
        uint32_t ph[4][4], pl[4][4];
#pragma unroll
        for (int j = 0; j < 4; j++) {
            split_pack(ph[j][0], pl[j][0], s[2 * j][0], s[2 * j][1]);
            split_pack(ph[j][1], pl[j][1], s[2 * j][2], s[2 * j][3]);
            split_pack(ph[j][2], pl[j][2], s[2 * j + 1][0], s[2 * j + 1][1]);
            split_pack(ph[j][3], pl[j][3], s[2 * j + 1][2], s[2 * j + 1][3]);
        }

        // ---- O += P V ----
#pragma unroll
        for (int j = 0; j < 4; j++) {
#pragma unroll
            for (int ndp = 0; ndp < 4; ndp++) {
                uint32_t off = SMEM_SWIZZLE_128B((j * 16 + vk_in) * 128 +
                                                 (ndp * 16 + vd_in) * 2);
                uint32_t vh4[4], vl4[4];
                ldsm_x4_t(vh4, base + AT_VH + off);
                ldsm_x4_t(vl4, base + AT_VL + off);
                mma16816(o[2 * ndp], ph[j], vh4 + 0);
                mma16816(o[2 * ndp], ph[j], vl4 + 0);
                mma16816(o[2 * ndp], pl[j], vh4 + 0);
                mma16816(o[2 * ndp + 1], ph[j], vh4 + 2);
                mma16816(o[2 * ndp + 1], ph[j], vl4 + 2);
                mma16816(o[2 * ndp + 1], pl[j], vh4 + 2);
            }
        }
    }

    float i0 = 1.f / l0, i1 = 1.f / l1;
    float* Og = g_O + (qtok + w * 16 + g) * MODEL_DIM + h * HDIM + tq2;
#pragma unroll
    for (int nd = 0; nd < 8; nd++) {
        *(float2*)(Og + nd * 8) = make_float2(o[nd][0] * i0, o[nd][1] * i0);
        *(float2*)(Og + 8 * MODEL_DIM + nd * 8) =
            make_float2(o[nd][2] * i1, o[nd][3] * i1);
    }
}

// ===========================================================================
// Launch
// ===========================================================================
extern "C" void kernel_launch(void* const* d_in, const int* in_sizes, int n_in,
                              void* d_out, int out_size) {
    const float* q   = (const float*)d_in[0];
    const float* k   = (const float*)d_in[1];
    const float* v   = (const float*)d_in[2];
    const int*   msk = (const int*)  d_in[3];
    const float* w_q = (const float*)d_in[4];
    const float* b_q = (const float*)d_in[5];
    const float* w_k = (const float*)d_in[6];
    const float* b_k = (const float*)d_in[7];
    const float* w_v = (const float*)d_in[8];
    const float* b_v = (const float*)d_in[9];
    const float* w_o = (const float*)d_in[10];
    const float* b_o = (const float*)d_in[11];
    float* out = (float*)d_out;

    float* pO;
    __nv_bfloat16 *pAhi, *pAlo, *pBhi, *pBlo;
    __nv_bfloat16 *pQh, *pQl, *pKh, *pKl, *pVh, *pVl, *pMB;
    cudaGetSymbolAddress((void**)&pO, g_O);
    cudaGetSymbolAddress((void**)&pAhi, g_Ahi);
    cudaGetSymbolAddress((void**)&pAlo, g_Alo);
    cudaGetSymbolAddress((void**)&pBhi, g_Bhi);
    cudaGetSymbolAddress((void**)&pBlo, g_Blo);
    cudaGetSymbolAddress((void**)&pQh, g_Qhi);
    cudaGetSymbolAddress((void**)&pQl, g_Qlo);
    cudaGetSymbolAddress((void**)&pKh, g_Khi);
    cudaGetSymbolAddress((void**)&pKl, g_Klo);
    cudaGetSymbolAddress((void**)&pVh, g_Vhi);
    cudaGetSymbolAddress((void**)&pVl, g_Vlo);
    cudaGetSymbolAddress((void**)&pMB, g_mb);

    cudaFuncSetAttribute(gemm_tc<true>,
                         cudaFuncAttributeMaxDynamicSharedMemorySize, G_SMEM_TOTAL);
    cudaFuncSetAttribute(gemm_tc<false>,
                         cudaFuncAttributeMaxDynamicSharedMemorySize, G_SMEM_TOTAL);
    cudaFuncSetAttribute(attn_tc,
                         cudaFuncAttributeMaxDynamicSharedMemorySize, AT_SMEM);

    const int act_blocks = (MROWS * MODEL_DIM / 4) / 256;   // 4096
    dim3 wt_grid(MODEL_DIM / 32, MODEL_DIM / 32);
    dim3 wt_block(32, 8);
    dim3 g_grid(MODEL_DIM / 128, MROWS / 128);              // (8, 32)

    conv_mask<<<(SEQ * SEQ / 4) / 256, 256>>>((const int4*)msk,
                                              (__nv_bfloat162*)pMB);

    // Q projection -> bf16 hi/lo
    conv_act<<<act_blocks, 256>>>((const float4*)q,
                                  (__nv_bfloat162*)pAhi, (__nv_bfloat162*)pAlo);
    conv_wt<<<wt_grid, wt_block>>>(w_q, pBhi, pBlo);
    gemm_tc<true><<<g_grid, 256, G_SMEM_TOTAL>>>(pAhi, pAlo, pBhi, pBlo, b_q,
                                                 nullptr, pQh, pQl);
    // K projection -> bf16 hi/lo
    conv_act<<<act_blocks, 256>>>((const float4*)k,
                                  (__nv_bfloat162*)pAhi, (__nv_bfloat162*)pAlo);
    conv_wt<<<wt_grid, wt_block>>>(w_k, pBhi, pBlo);
    gemm_tc<true><<<g_grid, 256, G_SMEM_TOTAL>>>(pAhi, pAlo, pBhi, pBlo, b_k,
                                                 nullptr, pKh, pKl);
    // V projection -> bf16 hi/lo
    conv_act<<<act_blocks, 256>>>((const float4*)v,
                                  (__nv_bfloat162*)pAhi, (__nv_bfloat162*)pAlo);
    conv_wt<<<wt_grid, wt_block>>>(w_v, pBhi, pBlo);
    gemm_tc<true><<<g_grid, 256, G_SMEM_TOTAL>>>(pAhi, pAlo, pBhi, pBlo, b_v,
                                                 nullptr, pVh, pVl);

    // Tensor-core flash attention
    dim3 agrid(SEQ / 64, BATCH * NHEAD);                    // (32, 32)
    attn_tc<<<agrid, 128, AT_SMEM>>>();

    // Output projection (fp32 out)
    conv_act<<<act_blocks, 256>>>((const float4*)pO,
                                  (__nv_bfloat162*)pAhi, (__nv_bfloat162*)pAlo);
    conv_wt<<<wt_grid, wt_block>>>(w_o, pBhi, pBlo);
    gemm_tc<false><<<g_grid, 256, G_SMEM_TOTAL>>>(pAhi, pAlo, pBhi, pBlo, b_o,
                                                  out, nullptr, nullptr);
}